// round 6
// baseline (speedup 1.0000x reference)
#include <cuda_runtime.h>
#include <cuda_bf16.h>
#include <cstdint>

#define D 64
#define MAXN 100000
#define MAXE 1200000
#define NEG_SLOPE 0.2f

// ---------------- scratch (static device globals; no allocation) ----------------
__device__ float    g_z[MAXN * D];     // transformed features z = xW^T + b
__device__ float    g_e[MAXE];         // edge scores, then exp values
__device__ float    g_s[MAXN];         // segment sums
__device__ unsigned g_mkey[MAXN];      // encoded segment max
__device__ float    g_wt[D * D];       // W transposed: g_wt[k*64 + j] = W[j*64 + k]

// order-preserving float <-> uint encoding for atomicMax
__device__ __forceinline__ unsigned fenc(float f) {
    unsigned u = __float_as_uint(f);
    return (u >> 31) ? ~u : (u | 0x80000000u);
}
__device__ __forceinline__ float fdec(unsigned k) {
    return (k >> 31) ? __uint_as_float(k & 0x7fffffffu) : __uint_as_float(~k);
}

// ---------------- init: zero out, s, mkey ----------------
__global__ void init_kernel(float* __restrict__ out, int N) {
    int i = blockIdx.x * blockDim.x + threadIdx.x;
    int total = N * D;
    if (i < total) out[i] = 0.0f;
    if (i < N) { g_s[i] = 0.0f; g_mkey[i] = 0u; }
}

// ---------------- transpose W (4096 elems, one-shot) ----------------
__global__ void transpose_w_kernel(const float* __restrict__ W) {
    int p = blockIdx.x * blockDim.x + threadIdx.x;
    if (p < D * D) {
        int j = p >> 6, k = p & 63;
        g_wt[k * D + j] = W[p];
    }
}

// ---------------- z = x @ W^T + b  (64x64 tile per block, 4x4 per thread) ----------------
__global__ __launch_bounds__(256) void gemm_kernel(const float* __restrict__ x,
                                                   const float* __restrict__ b,
                                                   int N) {
    __shared__ float Ws[D * D];   // Wt tile (whole W, transposed)
    __shared__ float Xs[64 * D];  // 64 rows of x

    int tid = threadIdx.x;
    int row0 = blockIdx.x * 64;

    #pragma unroll
    for (int p = tid; p < D * D; p += 256) Ws[p] = g_wt[p];

    #pragma unroll
    for (int p = tid; p < 64 * D; p += 256) {
        int r = p >> 6, k = p & 63;
        int gr = row0 + r;
        Xs[p] = (gr < N) ? x[gr * D + k] : 0.0f;
    }
    __syncthreads();

    int tx = tid & 15;   // column group: cols [4tx, 4tx+3]
    int ty = tid >> 4;   // row group:    rows [4ty, 4ty+3]

    float acc[4][4];
    #pragma unroll
    for (int r = 0; r < 4; r++)
        #pragma unroll
        for (int c = 0; c < 4; c++) acc[r][c] = 0.0f;

    #pragma unroll 8
    for (int k = 0; k < D; k++) {
        float4 w = *(const float4*)&Ws[k * D + tx * 4];
        #pragma unroll
        for (int r = 0; r < 4; r++) {
            float xv = Xs[(ty * 4 + r) * D + k];
            acc[r][0] = fmaf(xv, w.x, acc[r][0]);
            acc[r][1] = fmaf(xv, w.y, acc[r][1]);
            acc[r][2] = fmaf(xv, w.z, acc[r][2]);
            acc[r][3] = fmaf(xv, w.w, acc[r][3]);
        }
    }

    float4 bb = __ldg((const float4*)b + tx);
    #pragma unroll
    for (int r = 0; r < 4; r++) {
        int gr = row0 + ty * 4 + r;
        if (gr < N) {
            float4 o = make_float4(acc[r][0] + bb.x, acc[r][1] + bb.y,
                                   acc[r][2] + bb.z, acc[r][3] + bb.w);
            *(float4*)&g_z[gr * D + tx * 4] = o;
        }
    }
}

// ---------------- edge scores: e = att . lrelu(z_src + z_dst); atomicMax per dst ----------------
// 16 lanes per edge (2 edges per warp), float4 loads.
__global__ __launch_bounds__(256) void score_kernel(const int* __restrict__ ei,
                                                    const float* __restrict__ att,
                                                    int E) {
    int gt = blockIdx.x * blockDim.x + threadIdx.x;
    int lane = threadIdx.x & 31;
    int half = lane >> 4;
    int sub  = lane & 15;
    long long edge = ((long long)(gt >> 5)) * 2 + half;

    float v = 0.0f;
    int dst = 0;
    bool valid = (edge < E);
    if (valid) {
        int src = ei[edge];
        dst     = ei[E + edge];
        float4 a  = __ldg((const float4*)att + sub);
        float4 zs = *(const float4*)&g_z[(long long)src * D + sub * 4];
        float4 zd = *(const float4*)&g_z[(long long)dst * D + sub * 4];
        float u0 = zs.x + zd.x, u1 = zs.y + zd.y, u2 = zs.z + zd.z, u3 = zs.w + zd.w;
        u0 = (u0 > 0.f) ? u0 : NEG_SLOPE * u0;
        u1 = (u1 > 0.f) ? u1 : NEG_SLOPE * u1;
        u2 = (u2 > 0.f) ? u2 : NEG_SLOPE * u2;
        u3 = (u3 > 0.f) ? u3 : NEG_SLOPE * u3;
        v = a.x * u0 + a.y * u1 + a.z * u2 + a.w * u3;
    }
    // reduce within the 16-lane group (xor stays inside the group)
    #pragma unroll
    for (int off = 8; off > 0; off >>= 1)
        v += __shfl_xor_sync(0xffffffffu, v, off);

    if (valid && sub == 0) {
        g_e[edge] = v;
        atomicMax(&g_mkey[dst], fenc(v));
    }
}

// ---------------- exp + segment sum ----------------
__global__ __launch_bounds__(256) void exp_kernel(const int* __restrict__ ei, int E) {
    int i = blockIdx.x * blockDim.x + threadIdx.x;
    if (i < E) {
        int dst = ei[E + i];
        float m = fdec(g_mkey[dst]);
        float ex = expf(g_e[i] - m);
        g_e[i] = ex;
        atomicAdd(&g_s[dst], ex);
    }
}

// ---------------- aggregate: out[dst] += alpha * x[src], vector red ----------------
__global__ __launch_bounds__(256) void aggregate_kernel(const float* __restrict__ x,
                                                        const int* __restrict__ ei,
                                                        float* __restrict__ out,
                                                        int E) {
    int gt = blockIdx.x * blockDim.x + threadIdx.x;
    int lane = threadIdx.x & 31;
    int half = lane >> 4;
    int sub  = lane & 15;
    long long edge = ((long long)(gt >> 5)) * 2 + half;
    if (edge >= E) return;

    int src = ei[edge];
    int dst = ei[E + edge];
    float alpha = g_e[edge] / g_s[dst];

    float4 xv = __ldg((const float4*)(x + (long long)src * D) + sub);
    float r0 = alpha * xv.x, r1 = alpha * xv.y, r2 = alpha * xv.z, r3 = alpha * xv.w;

    float* p = out + (long long)dst * D + sub * 4;
    asm volatile("red.global.add.v4.f32 [%0], {%1, %2, %3, %4};"
                 :: "l"(p), "f"(r0), "f"(r1), "f"(r2), "f"(r3)
                 : "memory");
}

// ---------------- launch ----------------
extern "C" void kernel_launch(void* const* d_in, const int* in_sizes, int n_in,
                              void* d_out, int out_size) {
    const float* x   = (const float*)d_in[0];
    const int*   ei  = (const int*)d_in[1];
    const float* W   = (const float*)d_in[2];
    const float* b   = (const float*)d_in[3];
    const float* att = (const float*)d_in[4];
    float* out = (float*)d_out;

    int N = in_sizes[0] / D;
    int E = in_sizes[1] / 2;

    // init out/s/mkey
    {
        int total = N * D;
        init_kernel<<<(total + 255) / 256, 256>>>(out, N);
    }
    // transpose W
    transpose_w_kernel<<<(D * D + 255) / 256, 256>>>(W);
    // z = xW^T + b
    gemm_kernel<<<(N + 63) / 64, 256>>>(x, b, N);
    // edge scores + segment max
    {
        long long warps = ((long long)E + 1) / 2;
        long long threads = warps * 32;
        int blocks = (int)((threads + 255) / 256);
        score_kernel<<<blocks, 256>>>(ei, att, E);
    }
    // exp + segment sum
    exp_kernel<<<(E + 255) / 256, 256>>>(ei, E);
    // weighted aggregation
    {
        long long warps = ((long long)E + 1) / 2;
        long long threads = warps * 32;
        int blocks = (int)((threads + 255) / 256);
        aggregate_kernel<<<blocks, 256>>>(x, ei, out, E);
    }
}

// round 8
// speedup vs baseline: 1.4135x; 1.4135x over previous
#include <cuda_runtime.h>
#include <cuda_bf16.h>
#include <cstdint>

#define D 64
#define MAXN 100000
#define MAXE 1200000
#define NEG_SLOPE 0.2f

// ---------------- scratch (static device globals; no allocation) ----------------
__device__ float g_z[MAXN * D];   // transformed features z = xW^T + b
__device__ float g_s[MAXN];       // segment sums of exp(e)
__device__ float g_wt[D * D];     // W transposed: g_wt[k*64 + j] = W[j*64 + k]

// ---------------- init: zero out + s (float4 for out) ----------------
__global__ void init_kernel(float4* __restrict__ out4, int N) {
    int i = blockIdx.x * blockDim.x + threadIdx.x;
    int total4 = N * (D / 4);
    if (i < total4) out4[i] = make_float4(0.f, 0.f, 0.f, 0.f);
    if (i < N) g_s[i] = 0.0f;
}

// ---------------- transpose W (4096 elems, one-shot) ----------------
__global__ void transpose_w_kernel(const float* __restrict__ W) {
    int p = blockIdx.x * blockDim.x + threadIdx.x;
    if (p < D * D) {
        int j = p >> 6, k = p & 63;
        g_wt[k * D + j] = W[p];
    }
}

// ---------------- z = x @ W^T + b  (64x64 tile per block, 4x4 per thread) ----------------
__global__ __launch_bounds__(256) void gemm_kernel(const float* __restrict__ x,
                                                   const float* __restrict__ b,
                                                   int N) {
    __shared__ float Ws[D * D];   // Wt (whole, transposed)
    __shared__ float Xs[64 * D];  // 64 rows of x

    int tid = threadIdx.x;
    int row0 = blockIdx.x * 64;

    #pragma unroll
    for (int p = tid; p < D * D; p += 256) Ws[p] = g_wt[p];

    #pragma unroll
    for (int p = tid; p < 64 * D; p += 256) {
        int r = p >> 6, k = p & 63;
        int gr = row0 + r;
        Xs[p] = (gr < N) ? x[gr * D + k] : 0.0f;
    }
    __syncthreads();

    int tx = tid & 15;   // cols [4tx, 4tx+3]
    int ty = tid >> 4;   // rows [4ty, 4ty+3]

    float acc[4][4];
    #pragma unroll
    for (int r = 0; r < 4; r++)
        #pragma unroll
        for (int c = 0; c < 4; c++) acc[r][c] = 0.0f;

    #pragma unroll 8
    for (int k = 0; k < D; k++) {
        float4 w = *(const float4*)&Ws[k * D + tx * 4];
        #pragma unroll
        for (int r = 0; r < 4; r++) {
            float xv = Xs[(ty * 4 + r) * D + k];
            acc[r][0] = fmaf(xv, w.x, acc[r][0]);
            acc[r][1] = fmaf(xv, w.y, acc[r][1]);
            acc[r][2] = fmaf(xv, w.z, acc[r][2]);
            acc[r][3] = fmaf(xv, w.w, acc[r][3]);
        }
    }

    float4 bb = __ldg((const float4*)b + tx);
    #pragma unroll
    for (int r = 0; r < 4; r++) {
        int gr = row0 + ty * 4 + r;
        if (gr < N) {
            float4 o = make_float4(acc[r][0] + bb.x, acc[r][1] + bb.y,
                                   acc[r][2] + bb.z, acc[r][3] + bb.w);
            *(float4*)&g_z[gr * D + tx * 4] = o;
        }
    }
}

// ---------------- FUSED edge pass ----------------
// Per edge (16 lanes, 2 edges/warp):
//   v  = att . lrelu(z_src + z_dst)            (gathers, fma, 4x shfl.xor)
//   ex = __expf(v)                             (all 16 lanes hold v after xor-reduce)
//   red.global.add.v4  out[dst] += ex * x[src] (unnormalized accumulation)
//   lane0: atomicAdd(s[dst], ex)
// Normalization happens in a final tiny kernel: out[i] /= s[i].
// (Per-dst max shift cancels exactly in exp(e)/sum exp(e); |e| is small, no overflow.)
__global__ __launch_bounds__(256) void edge_kernel(const float* __restrict__ x,
                                                   const int* __restrict__ ei,
                                                   const float* __restrict__ att,
                                                   float* __restrict__ out,
                                                   int E) {
    int gt = blockIdx.x * blockDim.x + threadIdx.x;
    int lane = threadIdx.x & 31;
    int half = lane >> 4;
    int sub  = lane & 15;
    int edge = ((gt >> 5) << 1) + half;   // fits in int (E = 1.2M)

    bool valid = (edge < E);
    int src = 0, dst = 0;
    float v = 0.0f;
    if (valid) {
        src = __ldg(ei + edge);
        dst = __ldg(ei + E + edge);
        int zo = sub << 2;                         // float offset within row
        float4 a  = __ldg((const float4*)att + sub);
        float4 zs = *(const float4*)(g_z + (src << 6) + zo);
        float4 zd = *(const float4*)(g_z + (dst << 6) + zo);
        float u0 = zs.x + zd.x, u1 = zs.y + zd.y, u2 = zs.z + zd.z, u3 = zs.w + zd.w;
        u0 = (u0 > 0.f) ? u0 : NEG_SLOPE * u0;
        u1 = (u1 > 0.f) ? u1 : NEG_SLOPE * u1;
        u2 = (u2 > 0.f) ? u2 : NEG_SLOPE * u2;
        u3 = (u3 > 0.f) ? u3 : NEG_SLOPE * u3;
        v = a.x * u0 + a.y * u1 + a.z * u2 + a.w * u3;
    }
    // xor-reduction within the 16-lane group; every lane ends with the full dot
    #pragma unroll
    for (int off = 8; off > 0; off >>= 1)
        v += __shfl_xor_sync(0xffffffffu, v, off);

    if (!valid) return;

    float ex = __expf(v);

    float4 xv = __ldg((const float4*)(x + (src << 6)) + sub);
    float r0 = ex * xv.x, r1 = ex * xv.y, r2 = ex * xv.z, r3 = ex * xv.w;

    float* p = out + (dst << 6) + (sub << 2);
    asm volatile("red.global.add.v4.f32 [%0], {%1, %2, %3, %4};"
                 :: "l"(p), "f"(r0), "f"(r1), "f"(r2), "f"(r3)
                 : "memory");

    if (sub == 0) atomicAdd(&g_s[dst], ex);
}

// ---------------- normalize: out[i] /= s[i] (s==0 -> 0 for isolated nodes) ----------------
__global__ __launch_bounds__(256) void normalize_kernel(float4* __restrict__ out4, int N) {
    int i = blockIdx.x * blockDim.x + threadIdx.x;
    int total4 = N * (D / 4);
    if (i >= total4) return;
    float s = g_s[i >> 4];
    float inv = (s > 0.f) ? __frcp_rn(s) : 0.f;
    float4 v = out4[i];
    out4[i] = make_float4(v.x * inv, v.y * inv, v.z * inv, v.w * inv);
}

// ---------------- launch ----------------
extern "C" void kernel_launch(void* const* d_in, const int* in_sizes, int n_in,
                              void* d_out, int out_size) {
    const float* x   = (const float*)d_in[0];
    const int*   ei  = (const int*)d_in[1];
    const float* W   = (const float*)d_in[2];
    const float* b   = (const float*)d_in[3];
    const float* att = (const float*)d_in[4];
    float* out = (float*)d_out;

    int N = in_sizes[0] / D;
    int E = in_sizes[1] / 2;

    // init out + s
    {
        int total4 = N * (D / 4);
        init_kernel<<<(total4 + 255) / 256, 256>>>((float4*)out, N);
    }
    // transpose W
    transpose_w_kernel<<<(D * D + 255) / 256, 256>>>(W);
    // z = xW^T + b
    gemm_kernel<<<(N + 63) / 64, 256>>>(x, b, N);
    // fused edge pass: score + exp + weighted scatter + segment sum
    {
        long long warps = ((long long)E + 1) / 2;
        long long threads = warps * 32;
        int blocks = (int)((threads + 255) / 256);
        edge_kernel<<<blocks, 256>>>(x, ei, att, out, E);
    }
    // final normalization
    {
        int total4 = N * (D / 4);
        normalize_kernel<<<(total4 + 255) / 256, 256>>>((float4*)out, N);
    }
}

// round 9
// speedup vs baseline: 1.5732x; 1.1130x over previous
#include <cuda_runtime.h>
#include <cuda_bf16.h>
#include <cstdint>

#define D 64
#define MAXN 100000
#define MAXE 1200000
#define NEG_SLOPE 0.2f
#define SCAN_BLK 1024          // elements per scan block (256 thr x 4)
#define MAX_SCAN_BLOCKS 128

// ---------------- scratch (static device globals; no allocation) ----------------
__device__ float g_z[MAXN * D];       // z = xW^T + b
__device__ float g_wt[D * D];         // W transposed
__device__ int   g_cnt[MAXN];         // in-degree histogram
__device__ int   g_off[MAXN + 1];     // CSR offsets (exclusive)
__device__ int   g_cur[MAXN];         // scatter cursors
__device__ int   g_csr[MAXE];         // src ids grouped by dst
__device__ int   g_bsum[MAX_SCAN_BLOCKS];

// ---------------- prep: zero histogram + transpose W ----------------
__global__ void prep_kernel(const float* __restrict__ W, int N) {
    int i = blockIdx.x * blockDim.x + threadIdx.x;
    if (i < N) g_cnt[i] = 0;
    if (i < D * D) {
        int j = i >> 6, k = i & 63;
        g_wt[k * D + j] = W[i];
    }
}

// ---------------- z = x @ W^T + b (64x64 tile per block, 4x4 per thread) ----------------
__global__ __launch_bounds__(256) void gemm_kernel(const float* __restrict__ x,
                                                   const float* __restrict__ b,
                                                   int N) {
    __shared__ float Ws[D * D];
    __shared__ float Xs[64 * D];

    int tid = threadIdx.x;
    int row0 = blockIdx.x * 64;

    #pragma unroll
    for (int p = tid; p < D * D; p += 256) Ws[p] = g_wt[p];
    #pragma unroll
    for (int p = tid; p < 64 * D; p += 256) {
        int r = p >> 6, k = p & 63;
        int gr = row0 + r;
        Xs[p] = (gr < N) ? x[gr * D + k] : 0.0f;
    }
    __syncthreads();

    int tx = tid & 15;
    int ty = tid >> 4;

    float acc[4][4];
    #pragma unroll
    for (int r = 0; r < 4; r++)
        #pragma unroll
        for (int c = 0; c < 4; c++) acc[r][c] = 0.0f;

    #pragma unroll 8
    for (int k = 0; k < D; k++) {
        float4 w = *(const float4*)&Ws[k * D + tx * 4];
        #pragma unroll
        for (int r = 0; r < 4; r++) {
            float xv = Xs[(ty * 4 + r) * D + k];
            acc[r][0] = fmaf(xv, w.x, acc[r][0]);
            acc[r][1] = fmaf(xv, w.y, acc[r][1]);
            acc[r][2] = fmaf(xv, w.z, acc[r][2]);
            acc[r][3] = fmaf(xv, w.w, acc[r][3]);
        }
    }

    float4 bb = __ldg((const float4*)b + tx);
    #pragma unroll
    for (int r = 0; r < 4; r++) {
        int gr = row0 + ty * 4 + r;
        if (gr < N) {
            float4 o = make_float4(acc[r][0] + bb.x, acc[r][1] + bb.y,
                                   acc[r][2] + bb.z, acc[r][3] + bb.w);
            *(float4*)&g_z[gr * D + tx * 4] = o;
        }
    }
}

// ---------------- histogram of dst ----------------
__global__ __launch_bounds__(256) void hist_kernel(const int* __restrict__ ei, int E) {
    int e = blockIdx.x * blockDim.x + threadIdx.x;
    if (e < E) atomicAdd(&g_cnt[__ldg(ei + E + e)], 1);
}

// ---------------- scan phase 1: per-block inclusive scan (1024 elems/block) ----------------
__global__ __launch_bounds__(256) void scan1_kernel(int N) {
    __shared__ int sh[256];
    int t = threadIdx.x;
    int b = blockIdx.x;
    int i0 = b * SCAN_BLK + t * 4;

    int c[4];
    #pragma unroll
    for (int j = 0; j < 4; j++) c[j] = (i0 + j < N) ? g_cnt[i0 + j] : 0;
    int tsum = c[0] + c[1] + c[2] + c[3];

    sh[t] = tsum;
    __syncthreads();
    #pragma unroll
    for (int off = 1; off < 256; off <<= 1) {
        int v = (t >= off) ? sh[t - off] : 0;
        __syncthreads();
        sh[t] += v;
        __syncthreads();
    }
    int excl = sh[t] - tsum;   // exclusive prefix within block

    int run = excl;
    #pragma unroll
    for (int j = 0; j < 4; j++) {
        run += c[j];
        if (i0 + j < N) g_off[i0 + j + 1] = run;   // inclusive -> off[i+1]
    }
    if (t == 255) g_bsum[b] = sh[255];
    if (b == 0 && t == 0) g_off[0] = 0;
}

// ---------------- scan phase 2: scan block sums (single block) ----------------
__global__ __launch_bounds__(128) void scan2_kernel(int nb) {
    __shared__ int sh[128];
    int t = threadIdx.x;
    sh[t] = (t < nb) ? g_bsum[t] : 0;
    __syncthreads();
    #pragma unroll
    for (int off = 1; off < 128; off <<= 1) {
        int v = (t >= off) ? sh[t - off] : 0;
        __syncthreads();
        sh[t] += v;
        __syncthreads();
    }
    if (t < nb) g_bsum[t] = sh[t];
}

// ---------------- scan phase 3: fixup + init cursors ----------------
__global__ __launch_bounds__(256) void scan3_kernel(int N) {
    int i = blockIdx.x * blockDim.x + threadIdx.x;
    if (i >= N) return;
    int b = i / SCAN_BLK;
    int base = (b > 0) ? g_bsum[b - 1] : 0;
    int fin = g_off[i + 1] + base;
    g_off[i + 1] = fin;
    g_cur[i] = fin - g_cnt[i];    // = final g_off[i]
}

// ---------------- scatter edges into CSR by dst ----------------
__global__ __launch_bounds__(256) void scatter_kernel(const int* __restrict__ ei, int E) {
    int e = blockIdx.x * blockDim.x + threadIdx.x;
    if (e >= E) return;
    int src = __ldg(ei + e);
    int dst = __ldg(ei + E + e);
    int p = atomicAdd(&g_cur[dst], 1);
    g_csr[p] = src;
}

// ---------------- FUSED aggregate: one warp per dst ----------------
// z_dst & accumulator live in registers (16 lanes x float4 = row).
// Two half-warps process two edges simultaneously, sharing shfl instructions.
// out[dst] = (sum_e exp(v_e) * x[src_e]) / (sum_e exp(v_e)); zeros if degree 0.
__global__ __launch_bounds__(256) void aggregate_kernel(const float* __restrict__ x,
                                                        const float* __restrict__ att,
                                                        float* __restrict__ out,
                                                        int N) {
    int dst = blockIdx.x * 8 + (threadIdx.x >> 5);
    if (dst >= N) return;
    int lane = threadIdx.x & 31;
    int half = lane >> 4;
    int sub  = lane & 15;
    int zo = sub << 2;

    int beg = __ldg(&g_off[dst]);
    int end = __ldg(&g_off[dst + 1]);

    float4 a4 = __ldg((const float4*)att + sub);
    float4 zd = *(const float4*)(g_z + (dst << 6) + zo);

    float4 acc = make_float4(0.f, 0.f, 0.f, 0.f);
    float s = 0.f;

    for (int k2 = beg; k2 < end; k2 += 2) {
        int k = k2 + half;
        bool valid = (k < end);
        int src = valid ? __ldg(&g_csr[k]) : 0;

        float4 zs = *(const float4*)(g_z + (src << 6) + zo);
        float u0 = zs.x + zd.x, u1 = zs.y + zd.y, u2 = zs.z + zd.z, u3 = zs.w + zd.w;
        u0 = (u0 > 0.f) ? u0 : NEG_SLOPE * u0;
        u1 = (u1 > 0.f) ? u1 : NEG_SLOPE * u1;
        u2 = (u2 > 0.f) ? u2 : NEG_SLOPE * u2;
        u3 = (u3 > 0.f) ? u3 : NEG_SLOPE * u3;
        float pv = a4.x * u0 + a4.y * u1 + a4.z * u2 + a4.w * u3;

        // reduce within each 16-lane half (both edges share these shfls)
        #pragma unroll
        for (int off = 8; off > 0; off >>= 1)
            pv += __shfl_xor_sync(0xffffffffu, pv, off);

        float ex = valid ? __expf(pv) : 0.f;

        float4 xv = __ldg((const float4*)(x + (src << 6)) + sub);
        acc.x = fmaf(ex, xv.x, acc.x);
        acc.y = fmaf(ex, xv.y, acc.y);
        acc.z = fmaf(ex, xv.z, acc.z);
        acc.w = fmaf(ex, xv.w, acc.w);
        s += ex;
    }

    // combine the two halves
    acc.x += __shfl_xor_sync(0xffffffffu, acc.x, 16);
    acc.y += __shfl_xor_sync(0xffffffffu, acc.y, 16);
    acc.z += __shfl_xor_sync(0xffffffffu, acc.z, 16);
    acc.w += __shfl_xor_sync(0xffffffffu, acc.w, 16);
    s     += __shfl_xor_sync(0xffffffffu, s, 16);

    float inv = (s > 0.f) ? __frcp_rn(s) : 0.f;
    if (half == 0) {
        float4 o = make_float4(acc.x * inv, acc.y * inv, acc.z * inv, acc.w * inv);
        *(float4*)(out + (dst << 6) + zo) = o;
    }
}

// ---------------- launch ----------------
extern "C" void kernel_launch(void* const* d_in, const int* in_sizes, int n_in,
                              void* d_out, int out_size) {
    const float* x   = (const float*)d_in[0];
    const int*   ei  = (const int*)d_in[1];
    const float* W   = (const float*)d_in[2];
    const float* b   = (const float*)d_in[3];
    const float* att = (const float*)d_in[4];
    float* out = (float*)d_out;

    int N = in_sizes[0] / D;
    int E = in_sizes[1] / 2;
    int nb = (N + SCAN_BLK - 1) / SCAN_BLK;

    prep_kernel<<<(N + 255) / 256, 256>>>(W, N);
    gemm_kernel<<<(N + 63) / 64, 256>>>(x, b, N);
    hist_kernel<<<(E + 255) / 256, 256>>>(ei, E);
    scan1_kernel<<<nb, 256>>>(N);
    scan2_kernel<<<1, 128>>>(nb);
    scan3_kernel<<<(N + 255) / 256, 256>>>(N);
    scatter_kernel<<<(E + 255) / 256, 256>>>(ei, E);
    aggregate_kernel<<<(N + 7) / 8, 256>>>(x, att, out, N);
}